// round 9
// baseline (speedup 1.0000x reference)
#include <cuda_runtime.h>
#include <cstdint>

// SwitchLinear via portable mma.sync tf32 + ldmatrix fragment loads (sm_103-safe).
// out[t] = (W[route[t]] + Wf) @ x[t] + b[route[t]] + bf ; B=4096, IN=OUT=256, E=16.
//
// route_kernel (1 block): histogram/scan/scatter into 128-token m-tiles + bias sum.
// switch_gemm (<=192 blocks, 256 thr): tile = (128 tokens, 64 outs).
//   8 warps (4m x 2n), warp tile 32x32, mma.m16n8k8.tf32, fp32 accum.
//   Fragments via ldmatrix.x4 (b16 view). W+Wf summed+tf32-rounded in staging.
//   KC=32 double-buffered, rows padded to 36 floats (LDSM conflict-free).

#define B_TOK   4096
#define E_NUM   16
#define TM      128
#define TN      64
#define KC      32
#define NCH     8
#define MAX_MT  48
#define GRID_GEMM 192
#define RPAD    36
#define A_TILE_F (TM * RPAD)             // 4608 floats
#define B_TILE_F (TN * RPAD)             // 2304 floats
#define DSMEM_BYTES ((2 * A_TILE_F + 2 * B_TILE_F) * 4)   // 55296 B

__device__ int   g_sorted[B_TOK];
__device__ int   g_mt_e[MAX_MT];
__device__ int   g_mt_base[MAX_MT];
__device__ int   g_mt_cnt[MAX_MT];
__device__ int   g_nmt;
__device__ float g_bsum[E_NUM * 256];

static __device__ __forceinline__ uint32_t smem_u32(const void* p) {
    uint32_t a;
    asm("{ .reg .u64 t; cvta.to.shared.u64 t, %1; cvt.u32.u64 %0, t; }" : "=r"(a) : "l"(p));
    return a;
}
static __device__ __forceinline__ uint32_t f2tf(float x) {
    uint32_t u;
    asm("cvt.rna.tf32.f32 %0, %1;" : "=r"(u) : "f"(x));
    return u;
}
static __device__ __forceinline__ void mma_tf32(float* d, const uint32_t* a,
                                                uint32_t b0, uint32_t b1) {
    asm volatile(
        "mma.sync.aligned.m16n8k8.row.col.f32.tf32.tf32.f32 "
        "{%0,%1,%2,%3}, {%4,%5,%6,%7}, {%8,%9}, {%0,%1,%2,%3};"
        : "+f"(d[0]), "+f"(d[1]), "+f"(d[2]), "+f"(d[3])
        : "r"(a[0]), "r"(a[1]), "r"(a[2]), "r"(a[3]), "r"(b0), "r"(b1));
}
#define LDSM_X4(r0, r1, r2, r3, addr) \
    asm volatile("ldmatrix.sync.aligned.m8n8.x4.shared.b16 {%0,%1,%2,%3}, [%4];" \
                 : "=r"(r0), "=r"(r1), "=r"(r2), "=r"(r3) : "r"(addr))

// ---------------------------------------------------------------------------
// routing
// ---------------------------------------------------------------------------
__global__ void route_kernel(const int* __restrict__ route,
                             const float* __restrict__ bias,
                             const float* __restrict__ bfact) {
    __shared__ int cnt[E_NUM];
    __shared__ int cur[E_NUM];
    const int tid  = threadIdx.x;
    const int lane = tid & 31;

    if (tid < E_NUM) cnt[tid] = 0;
    __syncthreads();

    for (int t = tid; t < B_TOK; t += 1024) {
        int e = route[t];
        unsigned m = __match_any_sync(0xffffffffu, e);
        int leader = __ffs(m) - 1;
        if (lane == leader) atomicAdd(&cnt[e], __popc(m));
    }
    __syncthreads();

    if (tid < 32) {
        int c  = (tid < E_NUM) ? cnt[tid] : 0;
        int nt = (c + TM - 1) / TM;
        int cs = c, ts = nt;
        #pragma unroll
        for (int d = 1; d < 32; d <<= 1) {
            int v = __shfl_up_sync(0xffffffffu, cs, d);
            int w = __shfl_up_sync(0xffffffffu, ts, d);
            if (lane >= d) { cs += v; ts += w; }
        }
        int coff = cs - c, toff = ts - nt;
        if (tid < E_NUM) {
            cur[tid] = coff;
            for (int j = 0; j < nt; j++) {
                g_mt_e[toff + j]    = tid;
                g_mt_base[toff + j] = coff + j * TM;
                int rem = c - j * TM;
                g_mt_cnt[toff + j]  = rem < TM ? rem : TM;
            }
            if (tid == E_NUM - 1) g_nmt = ts;
        }
    }
    __syncthreads();

    for (int t = tid; t < B_TOK; t += 1024) {
        int e = route[t];
        unsigned m = __match_any_sync(0xffffffffu, e);
        int leader = __ffs(m) - 1;
        int rank = __popc(m & ((1u << lane) - 1u));
        int base = 0;
        if (lane == leader) base = atomicAdd(&cur[e], __popc(m));
        base = __shfl_sync(m, base, leader);
        g_sorted[base + rank] = t;
    }

    for (int i = tid; i < E_NUM * 256; i += 1024)
        g_bsum[i] = bias[i] + bfact[i & 255];
}

// ---------------------------------------------------------------------------
// gemm
// ---------------------------------------------------------------------------
__global__ __launch_bounds__(256, 1)
void switch_gemm(const float* __restrict__ input,
                 const float* __restrict__ weight,
                 const float* __restrict__ wfact,
                 float* __restrict__ out) {
    const int mt = blockIdx.x >> 2;
    const int nq = blockIdx.x & 3;            // 64-out quarter
    if (mt >= g_nmt) return;

    extern __shared__ float dsm[];
    // floats: A0 [0,4608) A1 [4608,9216) B0 [9216,11520) B1 [11520,13824)
    float* const A_s[2] = { dsm, dsm + A_TILE_F };
    float* const B_s[2] = { dsm + 2 * A_TILE_F, dsm + 2 * A_TILE_F + B_TILE_F };
    __shared__ int   toks[TM];
    __shared__ float bias_s[TN];

    const int tid  = threadIdx.x;
    const int wid  = tid >> 5;
    const int lane = tid & 31;
    const int wm   = wid & 3;                  // rows wm*32..+31
    const int wn   = wid >> 2;                 // outs wn*32..+31 (within quarter)

    const int e     = g_mt_e[mt];
    const int tbase = g_mt_base[mt];
    const int tcnt  = g_mt_cnt[mt];

    if (tid < TM) {
        int i = (tid < tcnt) ? tid : (tcnt - 1);
        toks[tid] = g_sorted[tbase + i];
    }
    if (tid < TN) bias_s[tid] = g_bsum[e * 256 + nq * TN + tid];
    __syncthreads();

    // ---- staging roles
    const int ar = tid >> 3;                   // A row base (0..31), rows ar+32i
    const int aq = tid & 7;                    // A 16B col
    const int br = tid >> 2;                   // B row (0..63)
    const int bq = (tid & 3) * 2;              // B 16B col pair
    int stok[4];
    #pragma unroll
    for (int i = 0; i < 4; i++) stok[i] = toks[ar + 32 * i];
    const float* __restrict__ wrow = weight + (size_t)e * 65536 + (size_t)(nq * TN + br) * 256;
    const float* __restrict__ frow = wfact + (size_t)(nq * TN + br) * 256;

    float4 rA[4], rB0, rB1;
    auto ldg = [&](int c) {
        #pragma unroll
        for (int i = 0; i < 4; i++)
            rA[i] = *(const float4*)(input + (size_t)stok[i] * 256 + c * KC + aq * 4);
        float4 w0 = *(const float4*)(wrow + c * KC + bq * 4);
        float4 w1 = *(const float4*)(wrow + c * KC + bq * 4 + 4);
        float4 f0 = *(const float4*)(frow + c * KC + bq * 4);
        float4 f1 = *(const float4*)(frow + c * KC + bq * 4 + 4);
        rB0.x = w0.x + f0.x; rB0.y = w0.y + f0.y; rB0.z = w0.z + f0.z; rB0.w = w0.w + f0.w;
        rB1.x = w1.x + f1.x; rB1.y = w1.y + f1.y; rB1.z = w1.z + f1.z; rB1.w = w1.w + f1.w;
    };
    auto sts = [&](int b) {
        #pragma unroll
        for (int i = 0; i < 4; i++) {
            uint4 cv;
            cv.x = f2tf(rA[i].x); cv.y = f2tf(rA[i].y);
            cv.z = f2tf(rA[i].z); cv.w = f2tf(rA[i].w);
            *(uint4*)(A_s[b] + (ar + 32 * i) * RPAD + aq * 4) = cv;
        }
        uint4 c0, c1;
        c0.x = f2tf(rB0.x); c0.y = f2tf(rB0.y); c0.z = f2tf(rB0.z); c0.w = f2tf(rB0.w);
        c1.x = f2tf(rB1.x); c1.y = f2tf(rB1.y); c1.z = f2tf(rB1.z); c1.w = f2tf(rB1.w);
        *(uint4*)(B_s[b] + br * RPAD + bq * 4)     = c0;
        *(uint4*)(B_s[b] + br * RPAD + bq * 4 + 4) = c1;
    };

    // ---- ldmatrix lane addresses (byte offsets from tile base)
    // A x4 (m16k8): lanes 0-15 -> rows lane&15 @k, lanes 16-31 -> same rows @k+4
    const int a_row_l = wm * 32 + (lane & 15);
    const int a_off_l = (a_row_l * RPAD + (lane >> 4) * 4) * 4;
    // B x4 (n16k8): lane groups of 8: {n0-7@k, n0-7@k+4, n8-15@k, n8-15@k+4}
    const int b_row_l = wn * 32 + ((lane >> 4) & 1) * 8 + (lane & 7);
    const int b_off_l = (b_row_l * RPAD + ((lane >> 3) & 1) * 4) * 4;

    const uint32_t A_u[2] = { smem_u32(A_s[0]) + a_off_l, smem_u32(A_s[1]) + a_off_l };
    const uint32_t B_u[2] = { smem_u32(B_s[0]) + b_off_l, smem_u32(B_s[1]) + b_off_l };

    float acc[2][4][4];
    #pragma unroll
    for (int am = 0; am < 2; am++)
        #pragma unroll
        for (int an = 0; an < 4; an++)
            #pragma unroll
            for (int j = 0; j < 4; j++) acc[am][an][j] = 0.0f;

    // prologue
    ldg(0);
    sts(0);
    ldg(1);
    __syncthreads();

    #pragma unroll 1
    for (int c = 0; c < NCH; c++) {
        if (c + 1 < NCH) sts((c + 1) & 1);
        if (c + 2 < NCH) ldg(c + 2);

        const uint32_t Ab = A_u[c & 1];
        const uint32_t Bb = B_u[c & 1];
        #pragma unroll
        for (int kk = 0; kk < 4; kk++) {
            const uint32_t ko = kk * 32;       // kk*8 floats
            uint32_t a0[4], a1[4], b0[4], b1r[4];
            LDSM_X4(a0[0], a0[1], a0[2], a0[3], Ab + ko);                    // m16 rows 0-15
            LDSM_X4(a1[0], a1[1], a1[2], a1[3], Ab + ko + 16 * RPAD * 4);    // rows 16-31
            LDSM_X4(b0[0], b0[1], b0[2], b0[3], Bb + ko);                    // n 0-15
            LDSM_X4(b1r[0], b1r[1], b1r[2], b1r[3], Bb + ko + 16 * RPAD * 4);// n 16-31
            mma_tf32(acc[0][0], a0, b0[0], b0[1]);
            mma_tf32(acc[0][1], a0, b0[2], b0[3]);
            mma_tf32(acc[0][2], a0, b1r[0], b1r[1]);
            mma_tf32(acc[0][3], a0, b1r[2], b1r[3]);
            mma_tf32(acc[1][0], a1, b0[0], b0[1]);
            mma_tf32(acc[1][1], a1, b0[2], b0[3]);
            mma_tf32(acc[1][2], a1, b1r[0], b1r[1]);
            mma_tf32(acc[1][3], a1, b1r[2], b1r[3]);
        }
        __syncthreads();
    }

    // epilogue: bias + store
    #pragma unroll
    for (int am = 0; am < 2; am++) {
        const int row0 = wm * 32 + am * 16 + (lane >> 2);
        const int row1 = row0 + 8;
        const bool v0 = row0 < tcnt;
        const bool v1 = row1 < tcnt;
        float* const orow0 = out + (size_t)toks[row0] * 256 + nq * TN;
        float* const orow1 = out + (size_t)toks[row1] * 256 + nq * TN;
        #pragma unroll
        for (int an = 0; an < 4; an++) {
            const int col = wn * 32 + an * 8 + 2 * (lane & 3);
            const float bx = bias_s[col], by = bias_s[col + 1];
            if (v0) *(float2*)(orow0 + col) = make_float2(acc[am][an][0] + bx, acc[am][an][1] + by);
            if (v1) *(float2*)(orow1 + col) = make_float2(acc[am][an][2] + bx, acc[am][an][3] + by);
        }
    }
}

// ---------------------------------------------------------------------------
extern "C" void kernel_launch(void* const* d_in, const int* in_sizes, int n_in,
                              void* d_out, int out_size) {
    const float* input  = (const float*)d_in[0];
    const int*   route  = (const int*)d_in[1];
    const float* weight = (const float*)d_in[2];
    const float* wfact  = (const float*)d_in[3];
    const float* bias   = (const float*)d_in[4];
    const float* bfact  = (const float*)d_in[5];
    float* out = (float*)d_out;

    cudaFuncSetAttribute(switch_gemm, cudaFuncAttributeMaxDynamicSharedMemorySize,
                         DSMEM_BYTES);

    route_kernel<<<1, 1024>>>(route, bias, bfact);
    switch_gemm<<<GRID_GEMM, 256, DSMEM_BYTES>>>(input, weight, wfact, out);
}

// round 10
// speedup vs baseline: 1.1469x; 1.1469x over previous
#include <cuda_runtime.h>
#include <cstdint>

// SwitchLinear via portable mma.sync tf32 + ldmatrix (sm_103-safe PTX).
// out[t] = (W[route[t]] + Wf) @ x[t] + b[route[t]] + bf ; B=4096, IN=OUT=256, E=16.
//
// route_kernel (1 block): histogram/scan/scatter into 64-token m-tiles + bias sum.
// switch_gemm (<=160 blocks, 512 thr): tile = (64 tokens, 128 outs).
//   16 warps (4m x 4n), warp tile 16x32, mma.m16n8k8.tf32, fp32 accum.
//   Fragments via ldmatrix.x4. W+Wf summed + tf32(rna)-rounded during staging.
//   KC=32 double-buffered, rows padded to 36 floats (LDSM conflict-free).

#define B_TOK   4096
#define E_NUM   16
#define TM      64
#define TN      128
#define KC      32
#define NCH     8
#define MAX_MT  80
#define GRID_GEMM 160
#define RPAD    36
#define A_TILE_F (TM * RPAD)             // 2304 floats
#define B_TILE_F (TN * RPAD)             // 4608 floats
#define DSMEM_BYTES ((2 * A_TILE_F + 2 * B_TILE_F) * 4)   // 55296 B

__device__ int   g_sorted[B_TOK];
__device__ int   g_mt_e[MAX_MT];
__device__ int   g_mt_base[MAX_MT];
__device__ int   g_mt_cnt[MAX_MT];
__device__ int   g_nmt;
__device__ float g_bsum[E_NUM * 256];

static __device__ __forceinline__ uint32_t smem_u32(const void* p) {
    uint32_t a;
    asm("{ .reg .u64 t; cvta.to.shared.u64 t, %1; cvt.u32.u64 %0, t; }" : "=r"(a) : "l"(p));
    return a;
}
static __device__ __forceinline__ uint32_t f2tf(float x) {
    uint32_t u;
    asm("cvt.rna.tf32.f32 %0, %1;" : "=r"(u) : "f"(x));
    return u;
}
static __device__ __forceinline__ void mma_tf32(float* d, const uint32_t* a,
                                                uint32_t b0, uint32_t b1) {
    asm volatile(
        "mma.sync.aligned.m16n8k8.row.col.f32.tf32.tf32.f32 "
        "{%0,%1,%2,%3}, {%4,%5,%6,%7}, {%8,%9}, {%0,%1,%2,%3};"
        : "+f"(d[0]), "+f"(d[1]), "+f"(d[2]), "+f"(d[3])
        : "r"(a[0]), "r"(a[1]), "r"(a[2]), "r"(a[3]), "r"(b0), "r"(b1));
}
#define LDSM_X4(r0, r1, r2, r3, addr) \
    asm volatile("ldmatrix.sync.aligned.m8n8.x4.shared.b16 {%0,%1,%2,%3}, [%4];" \
                 : "=r"(r0), "=r"(r1), "=r"(r2), "=r"(r3) : "r"(addr))

// ---------------------------------------------------------------------------
// routing
// ---------------------------------------------------------------------------
__global__ void route_kernel(const int* __restrict__ route,
                             const float* __restrict__ bias,
                             const float* __restrict__ bfact) {
    __shared__ int cnt[E_NUM];
    __shared__ int cur[E_NUM];
    const int tid  = threadIdx.x;
    const int lane = tid & 31;

    if (tid < E_NUM) cnt[tid] = 0;
    __syncthreads();

    for (int t = tid; t < B_TOK; t += 1024) {
        int e = route[t];
        unsigned m = __match_any_sync(0xffffffffu, e);
        int leader = __ffs(m) - 1;
        if (lane == leader) atomicAdd(&cnt[e], __popc(m));
    }
    __syncthreads();

    if (tid < 32) {
        int c  = (tid < E_NUM) ? cnt[tid] : 0;
        int nt = (c + TM - 1) / TM;
        int cs = c, ts = nt;
        #pragma unroll
        for (int d = 1; d < 32; d <<= 1) {
            int v = __shfl_up_sync(0xffffffffu, cs, d);
            int w = __shfl_up_sync(0xffffffffu, ts, d);
            if (lane >= d) { cs += v; ts += w; }
        }
        int coff = cs - c, toff = ts - nt;
        if (tid < E_NUM) {
            cur[tid] = coff;
            for (int j = 0; j < nt; j++) {
                g_mt_e[toff + j]    = tid;
                g_mt_base[toff + j] = coff + j * TM;
                int rem = c - j * TM;
                g_mt_cnt[toff + j]  = rem < TM ? rem : TM;
            }
            if (tid == E_NUM - 1) g_nmt = ts;
        }
    }
    __syncthreads();

    for (int t = tid; t < B_TOK; t += 1024) {
        int e = route[t];
        unsigned m = __match_any_sync(0xffffffffu, e);
        int leader = __ffs(m) - 1;
        int rank = __popc(m & ((1u << lane) - 1u));
        int base = 0;
        if (lane == leader) base = atomicAdd(&cur[e], __popc(m));
        base = __shfl_sync(m, base, leader);
        g_sorted[base + rank] = t;
    }

    for (int i = tid; i < E_NUM * 256; i += 1024)
        g_bsum[i] = bias[i] + bfact[i & 255];
}

// ---------------------------------------------------------------------------
// gemm
// ---------------------------------------------------------------------------
__global__ __launch_bounds__(512, 1)
void switch_gemm(const float* __restrict__ input,
                 const float* __restrict__ weight,
                 const float* __restrict__ wfact,
                 float* __restrict__ out) {
    const int mt = blockIdx.x >> 1;
    const int nh = blockIdx.x & 1;            // 128-out half
    if (mt >= g_nmt) return;

    extern __shared__ float dsm[];
    // floats: A0 [0,2304) A1 [2304,4608) B0 [4608,9216) B1 [9216,13824)
    float* const A_s[2] = { dsm, dsm + A_TILE_F };
    float* const B_s[2] = { dsm + 2 * A_TILE_F, dsm + 2 * A_TILE_F + B_TILE_F };
    __shared__ int   toks[TM];
    __shared__ float bias_s[TN];

    const int tid  = threadIdx.x;
    const int wid  = tid >> 5;
    const int lane = tid & 31;
    const int wm   = wid & 3;                  // rows wm*16..+15
    const int wn   = wid >> 2;                 // outs wn*32..+31 (within half)

    const int e     = g_mt_e[mt];
    const int tbase = g_mt_base[mt];
    const int tcnt  = g_mt_cnt[mt];

    if (tid < TM) {
        int i = (tid < tcnt) ? tid : (tcnt - 1);
        toks[tid] = g_sorted[tbase + i];
    }
    if (tid < TN) bias_s[tid] = g_bsum[e * 256 + nh * TN + tid];
    __syncthreads();

    // ---- staging roles (512 threads)
    const int ar = tid >> 3;                   // A row 0..63
    const int aq = tid & 7;                    // A 16B col
    const int br = tid >> 2;                   // B row 0..127
    const int bq = tid & 3;                    // B 32B col pair
    const float* __restrict__ airow = input + (size_t)toks[ar] * 256;
    const float* __restrict__ wrow  = weight + (size_t)e * 65536 + (size_t)(nh * TN + br) * 256;
    const float* __restrict__ frow  = wfact + (size_t)(nh * TN + br) * 256;

    float4 rA, rB0, rB1;
    auto ldg = [&](int c) {
        rA = *(const float4*)(airow + c * KC + aq * 4);
        float4 w0 = *(const float4*)(wrow + c * KC + bq * 8);
        float4 w1 = *(const float4*)(wrow + c * KC + bq * 8 + 4);
        float4 f0 = *(const float4*)(frow + c * KC + bq * 8);
        float4 f1 = *(const float4*)(frow + c * KC + bq * 8 + 4);
        rB0.x = w0.x + f0.x; rB0.y = w0.y + f0.y; rB0.z = w0.z + f0.z; rB0.w = w0.w + f0.w;
        rB1.x = w1.x + f1.x; rB1.y = w1.y + f1.y; rB1.z = w1.z + f1.z; rB1.w = w1.w + f1.w;
    };
    auto sts = [&](int b) {
        uint4 ca;
        ca.x = f2tf(rA.x); ca.y = f2tf(rA.y); ca.z = f2tf(rA.z); ca.w = f2tf(rA.w);
        *(uint4*)(A_s[b] + ar * RPAD + aq * 4) = ca;
        uint4 c0, c1;
        c0.x = f2tf(rB0.x); c0.y = f2tf(rB0.y); c0.z = f2tf(rB0.z); c0.w = f2tf(rB0.w);
        c1.x = f2tf(rB1.x); c1.y = f2tf(rB1.y); c1.z = f2tf(rB1.z); c1.w = f2tf(rB1.w);
        *(uint4*)(B_s[b] + br * RPAD + bq * 8)     = c0;
        *(uint4*)(B_s[b] + br * RPAD + bq * 8 + 4) = c1;
    };

    // ---- ldmatrix lane addresses (byte offsets)
    // A x4 (m16k8): lanes 0-15 -> rows 0-15 @k, lanes 16-31 -> same rows @k+4
    const int a_off_l = ((wm * 16 + (lane & 15)) * RPAD + (lane >> 4) * 4) * 4;
    // B x4 (n16k8): lane octets -> {n0-7@k, n0-7@k+4, n8-15@k, n8-15@k+4}
    const int b_row_l = wn * 32 + ((lane >> 4) & 1) * 8 + (lane & 7);
    const int b_off_l = (b_row_l * RPAD + ((lane >> 3) & 1) * 4) * 4;

    const uint32_t A_u[2] = { smem_u32(A_s[0]) + a_off_l, smem_u32(A_s[1]) + a_off_l };
    const uint32_t B_u[2] = { smem_u32(B_s[0]) + b_off_l, smem_u32(B_s[1]) + b_off_l };

    float acc[4][4];
    #pragma unroll
    for (int an = 0; an < 4; an++)
        #pragma unroll
        for (int j = 0; j < 4; j++) acc[an][j] = 0.0f;

    // prologue
    ldg(0);
    sts(0);
    ldg(1);
    __syncthreads();

    #pragma unroll 1
    for (int c = 0; c < NCH; c++) {
        if (c + 1 < NCH) sts((c + 1) & 1);     // regs hold chunk c+1; writes other buffer
        if (c + 2 < NCH) ldg(c + 2);           // in flight under compute

        const uint32_t Ab = A_u[c & 1];
        const uint32_t Bb = B_u[c & 1];
        #pragma unroll
        for (int kk = 0; kk < 4; kk++) {
            const uint32_t ko = kk * 32;       // kk*8 floats
            uint32_t a0[4], b0[4], b1r[4];
            LDSM_X4(a0[0], a0[1], a0[2], a0[3], Ab + ko);                     // m16
            LDSM_X4(b0[0], b0[1], b0[2], b0[3], Bb + ko);                     // n 0-15
            LDSM_X4(b1r[0], b1r[1], b1r[2], b1r[3], Bb + ko + 16 * RPAD * 4); // n 16-31
            mma_tf32(acc[0], a0, b0[0], b0[1]);
            mma_tf32(acc[1], a0, b0[2], b0[3]);
            mma_tf32(acc[2], a0, b1r[0], b1r[1]);
            mma_tf32(acc[3], a0, b1r[2], b1r[3]);
        }
        __syncthreads();
    }

    // epilogue: bias + store
    const int row0 = wm * 16 + (lane >> 2);
    const int row1 = row0 + 8;
    const bool v0 = row0 < tcnt;
    const bool v1 = row1 < tcnt;
    float* const orow0 = out + (size_t)toks[row0] * 256 + nh * TN;
    float* const orow1 = out + (size_t)toks[row1] * 256 + nh * TN;
    #pragma unroll
    for (int an = 0; an < 4; an++) {
        const int col = wn * 32 + an * 8 + 2 * (lane & 3);
        const float bx = bias_s[col], by = bias_s[col + 1];
        if (v0) *(float2*)(orow0 + col) = make_float2(acc[an][0] + bx, acc[an][1] + by);
        if (v1) *(float2*)(orow1 + col) = make_float2(acc[an][2] + bx, acc[an][3] + by);
    }
}

// ---------------------------------------------------------------------------
extern "C" void kernel_launch(void* const* d_in, const int* in_sizes, int n_in,
                              void* d_out, int out_size) {
    const float* input  = (const float*)d_in[0];
    const int*   route  = (const int*)d_in[1];
    const float* weight = (const float*)d_in[2];
    const float* wfact  = (const float*)d_in[3];
    const float* bias   = (const float*)d_in[4];
    const float* bfact  = (const float*)d_in[5];
    float* out = (float*)d_out;

    cudaFuncSetAttribute(switch_gemm, cudaFuncAttributeMaxDynamicSharedMemorySize,
                         DSMEM_BYTES);

    route_kernel<<<1, 1024>>>(route, bias, bfact);
    switch_gemm<<<GRID_GEMM, 512, DSMEM_BYTES>>>(input, weight, wfact, out);
}